// round 1
// baseline (speedup 1.0000x reference)
#include <cuda_runtime.h>
#include <cstdint>

namespace {

constexpr int Bsz = 512, Msl = 32, DIN = 1024, DH = 4096, DOUT = 1024;
constexpr int BM = 128, BN = 128, BK = 32;
constexpr int ASTRIDE = BM + 1;   // 129: pad to break LDS bank conflicts
constexpr int BSTRIDE = BN + 4;   // 132: keeps uint4 STS 16B-aligned

// Intermediate h: [m][b][dh], 512*32*4096 floats = 268 MB device scratch.
__device__ float g_h[(size_t)Bsz * Msl * DH];

__device__ __forceinline__ uint32_t f2tf(float f) {
    uint32_t u;
    asm("cvt.rna.tf32.f32 %0, %1;" : "=r"(u) : "f"(f));
    return u;
}

// C[Mrows,N] = A[Mrows,K] * B[K,N] + bias[N], optional ReLU.
// Batched over blockIdx.z (slot). All dims divide tiles exactly for this problem.
template<bool RELU>
__global__ void __launch_bounds__(256)
gemm_tf32(const float* __restrict__ Ag, const float* __restrict__ Bg,
          const float* __restrict__ biasg, float* __restrict__ Cg,
          int K,
          long aBatch, int lda,
          long bBatch, int ldb,
          long biasBatch,
          long cBatch, int ldc)
{
    __shared__ uint32_t As[BK][ASTRIDE];  // [k][m], tf32 bits
    __shared__ uint32_t Bs[BK][BSTRIDE];  // [k][n], tf32 bits

    const int tid  = threadIdx.x;
    const int lane = tid & 31, warp = tid >> 5;
    const int g = lane >> 2, tg = lane & 3;
    const int wm = warp & 3, wn = warp >> 2;      // 4 warps (m) x 2 warps (n)

    const int m0 = blockIdx.y * BM;
    const int n0 = blockIdx.x * BN;
    const float* A    = Ag    + (size_t)blockIdx.z * aBatch;
    const float* Bp   = Bg    + (size_t)blockIdx.z * bBatch;
    const float* bias = biasg + (size_t)blockIdx.z * biasBatch;
    float*       C    = Cg    + (size_t)blockIdx.z * cBatch;

    // global-load assignments
    const int arow = tid >> 3;     // 0..31 (+32 per iter): A tile row
    const int akg  = tid & 7;      // float4 group along k
    const int bkr  = tid >> 5;     // 0..7 (+8 per iter): B tile k-row
    const int bnc  = tid & 31;     // float4 group along n

    float4 ra[4], rb[4];
    float acc[2][8][4];
    #pragma unroll
    for (int i = 0; i < 2; i++)
        #pragma unroll
        for (int j = 0; j < 8; j++)
            #pragma unroll
            for (int q = 0; q < 4; q++) acc[i][j][q] = 0.f;

    const int ktiles = K / BK;

    auto ldgA = [&](int k0) {
        #pragma unroll
        for (int it = 0; it < 4; ++it) {
            int r = arow + it * 32;
            ra[it] = *(const float4*)(A + (size_t)(m0 + r) * lda + k0 + akg * 4);
        }
    };
    auto ldgB = [&](int k0) {
        #pragma unroll
        for (int it = 0; it < 4; ++it) {
            int kr = bkr + it * 8;
            rb[it] = *(const float4*)(Bp + (size_t)(k0 + kr) * ldb + n0 + bnc * 4);
        }
    };
    auto stsA = [&]() {
        #pragma unroll
        for (int it = 0; it < 4; ++it) {
            int r = arow + it * 32;
            As[akg * 4 + 0][r] = f2tf(ra[it].x);
            As[akg * 4 + 1][r] = f2tf(ra[it].y);
            As[akg * 4 + 2][r] = f2tf(ra[it].z);
            As[akg * 4 + 3][r] = f2tf(ra[it].w);
        }
    };
    auto stsB = [&]() {
        #pragma unroll
        for (int it = 0; it < 4; ++it) {
            int kr = bkr + it * 8;
            uint4 v;
            v.x = f2tf(rb[it].x); v.y = f2tf(rb[it].y);
            v.z = f2tf(rb[it].z); v.w = f2tf(rb[it].w);
            *(uint4*)&Bs[kr][bnc * 4] = v;
        }
    };

    auto compute = [&]() {
        #pragma unroll
        for (int ks = 0; ks < 4; ++ks) {
            uint32_t af[2][4], bf[8][2];
            #pragma unroll
            for (int mt = 0; mt < 2; ++mt) {
                int r = wm * 32 + mt * 16 + g;
                af[mt][0] = As[ks * 8 + tg    ][r];
                af[mt][1] = As[ks * 8 + tg    ][r + 8];
                af[mt][2] = As[ks * 8 + tg + 4][r];
                af[mt][3] = As[ks * 8 + tg + 4][r + 8];
            }
            #pragma unroll
            for (int nt = 0; nt < 8; ++nt) {
                int c = wn * 64 + nt * 8 + g;
                bf[nt][0] = Bs[ks * 8 + tg    ][c];
                bf[nt][1] = Bs[ks * 8 + tg + 4][c];
            }
            #pragma unroll
            for (int mt = 0; mt < 2; ++mt)
                #pragma unroll
                for (int nt = 0; nt < 8; ++nt)
                    asm volatile(
                        "mma.sync.aligned.m16n8k8.row.col.f32.tf32.tf32.f32 "
                        "{%0,%1,%2,%3}, {%4,%5,%6,%7}, {%8,%9}, {%0,%1,%2,%3};\n"
                        : "+f"(acc[mt][nt][0]), "+f"(acc[mt][nt][1]),
                          "+f"(acc[mt][nt][2]), "+f"(acc[mt][nt][3])
                        : "r"(af[mt][0]), "r"(af[mt][1]),
                          "r"(af[mt][2]), "r"(af[mt][3]),
                          "r"(bf[nt][0]), "r"(bf[nt][1]));
        }
    };

    // register-staged pipeline: LDG(t+1) issued before compute(t)
    ldgA(0); ldgB(0);
    stsA();  stsB();
    __syncthreads();
    for (int kt = 0; kt < ktiles; ++kt) {
        const int next = kt + 1;
        if (next < ktiles) { ldgA(next * BK); ldgB(next * BK); }
        compute();
        __syncthreads();
        if (next < ktiles) { stsA(); stsB(); __syncthreads(); }
    }

    // epilogue: +bias, optional relu, float2 stores
    #pragma unroll
    for (int mt = 0; mt < 2; ++mt) {
        int r = m0 + wm * 32 + mt * 16 + g;
        #pragma unroll
        for (int nt = 0; nt < 8; ++nt) {
            int c = n0 + wn * 64 + nt * 8 + tg * 2;
            float b0v = bias[c], b1v = bias[c + 1];
            float v0 = acc[mt][nt][0] + b0v;
            float v1 = acc[mt][nt][1] + b1v;
            float v2 = acc[mt][nt][2] + b0v;
            float v3 = acc[mt][nt][3] + b1v;
            if (RELU) {
                v0 = fmaxf(v0, 0.f); v1 = fmaxf(v1, 0.f);
                v2 = fmaxf(v2, 0.f); v3 = fmaxf(v3, 0.f);
            }
            float2 p0; p0.x = v0; p0.y = v1;
            float2 p1; p1.x = v2; p1.y = v3;
            *(float2*)(C + (size_t)r * ldc + c)       = p0;
            *(float2*)(C + (size_t)(r + 8) * ldc + c) = p1;
        }
    }
}

} // anonymous namespace

extern "C" void kernel_launch(void* const* d_in, const int* in_sizes, int n_in,
                              void* d_out, int out_size) {
    (void)in_sizes; (void)n_in; (void)out_size;
    const float* x  = (const float*)d_in[0];  // [B, M, DIN]
    const float* W1 = (const float*)d_in[1];  // [M, DIN, DH]
    const float* b1 = (const float*)d_in[2];  // [M, DH]
    const float* W2 = (const float*)d_in[3];  // [M, DH, DOUT]
    const float* b2 = (const float*)d_in[4];  // [M, DOUT]
    float* out = (float*)d_out;               // [B, M, DOUT]

    float* h = nullptr;
    cudaGetSymbolAddress((void**)&h, g_h);

    dim3 blk(256);

    // Layer 1: per slot m, [512,1024] x [1024,4096] + b1, ReLU -> h[m][b][:]
    dim3 g1(DH / BN, Bsz / BM, Msl);
    gemm_tf32<true><<<g1, blk>>>(
        x, W1, b1, h, DIN,
        /*aBatch*/ (long)DIN,        /*lda*/ Msl * DIN,
        /*bBatch*/ (long)DIN * DH,   /*ldb*/ DH,
        /*biasBatch*/ (long)DH,
        /*cBatch*/ (long)Bsz * DH,   /*ldc*/ DH);

    // Layer 2: per slot m, [512,4096] x [4096,1024] + b2 -> out[b][m][:]
    dim3 g2(DOUT / BN, Bsz / BM, Msl);
    gemm_tf32<false><<<g2, blk>>>(
        h, W2, b2, out, DH,
        /*aBatch*/ (long)Bsz * DH,   /*lda*/ DH,
        /*bBatch*/ (long)DH * DOUT,  /*ldb*/ DOUT,
        /*biasBatch*/ (long)DOUT,
        /*cBatch*/ (long)DOUT,       /*ldc*/ Msl * DOUT);
}

// round 3
// speedup vs baseline: 1.2702x; 1.2702x over previous
#include <cuda_runtime.h>
#include <cstdint>

namespace {

constexpr int Bsz = 512, Msl = 32, DIN = 1024, DH = 4096, DOUT = 1024;
constexpr int BM = 128, BN = 128, BK = 32;
constexpr int TILE_B = 128 * BK * 4;      // 16 KB per operand tile
constexpr int STAGE  = 2 * TILE_B;        // A + B = 32 KB
constexpr int SMEM_DYN = 2 * STAGE;       // 2-stage ping-pong = 64 KB

// Intermediate h: [m][b][dh]
__device__ float g_h[(size_t)Bsz * Msl * DH];

__device__ __forceinline__ uint32_t f2tf(float f) {
    uint32_t u; asm("cvt.rna.tf32.f32 %0, %1;" : "=r"(u) : "f"(f)); return u;
}
__device__ __forceinline__ uint32_t smem_u32(const void* p) {
    uint32_t a;
    asm("{ .reg .u64 t; cvta.to.shared.u64 t, %1; cvt.u32.u64 %0, t; }" : "=r"(a) : "l"(p));
    return a;
}
__device__ __forceinline__ void ldsm4(uint32_t r[4], uint32_t addr) {
    asm volatile("ldmatrix.sync.aligned.m8n8.x4.shared.b16 {%0,%1,%2,%3}, [%4];"
                 : "=r"(r[0]), "=r"(r[1]), "=r"(r[2]), "=r"(r[3]) : "r"(addr));
}
__device__ __forceinline__ void mma_tf32(float acc[4], const uint32_t a[4],
                                         uint32_t b0, uint32_t b1) {
    asm volatile(
        "mma.sync.aligned.m16n8k8.row.col.f32.tf32.tf32.f32 "
        "{%0,%1,%2,%3}, {%4,%5,%6,%7}, {%8,%9}, {%0,%1,%2,%3};\n"
        : "+f"(acc[0]), "+f"(acc[1]), "+f"(acc[2]), "+f"(acc[3])
        : "r"(a[0]), "r"(a[1]), "r"(a[2]), "r"(a[3]), "r"(b0), "r"(b1));
}

// C[BM,BN] tile of A[*,K] x W[K,*] (+bias, optional ReLU), batched over blockIdx.z.
// A rows are K-contiguous (stride lda). W rows are n-contiguous (stride ldw).
// Smem: A as [m][k] K-major SW-xor, B as [n][k] K-major SW-xor (transposed on store).
template<bool RELU>
__global__ void __launch_bounds__(256, 2)
gemm_tf32(const float* __restrict__ Ag, const float* __restrict__ Wg,
          const float* __restrict__ biasg, float* __restrict__ Cg,
          int K,
          long aBatch, int lda, long wBatch, int ldw,
          long biasBatch, long cBatch, int ldc)
{
    extern __shared__ char sm[];
    const uint32_t sb = smem_u32(sm);

    const int tid  = threadIdx.x;
    const int lane = tid & 31, warp = tid >> 5;
    const int g = lane >> 2, tg = lane & 3;
    const int wm = warp & 3, wn = warp >> 2;          // 4 (m) x 2 (n) warps

    const int m0 = blockIdx.y * BM;
    const int n0 = blockIdx.x * BN;
    const float* A    = Ag    + (size_t)blockIdx.z * aBatch;
    const float* W    = Wg    + (size_t)blockIdx.z * wBatch;
    const float* bias = biasg + (size_t)blockIdx.z * biasBatch;
    float*       C    = Cg    + (size_t)blockIdx.z * cBatch;

    // LDG assignments
    const int a_kg = tid & 7;          // 16B group within 128B k-row
    const int a_r0 = tid >> 3;         // row r0 (+32 per it)
    const int b_n  = (tid & 31) * 4;   // n base of this thread's 4x4 block
    const int b_k0 = (tid >> 5) * 4;   // k base of 4x4 block (0..28)

    // ldmatrix per-thread pieces
    const int lrow = lane & 15;
    const int lkh  = (lane >> 4) << 4;  // 0 or 16 bytes (k half)

    float acc[2][8][4];
    #pragma unroll
    for (int i = 0; i < 2; i++)
        #pragma unroll
        for (int j = 0; j < 8; j++)
            #pragma unroll
            for (int q = 0; q < 4; q++) acc[i][j][q] = 0.f;

    float4 ra[4], rb[4];

    auto ldgA = [&](int k0) {
        #pragma unroll
        for (int it = 0; it < 4; ++it) {
            const int r = a_r0 + it * 32;
            ra[it] = *(const float4*)(A + (size_t)(m0 + r) * lda + k0 + a_kg * 4);
        }
    };
    auto ldgB = [&](int k0) {
        const float* wp = W + (size_t)(k0 + b_k0) * ldw + n0 + b_n;
        #pragma unroll
        for (int j = 0; j < 4; ++j)
            rb[j] = *(const float4*)(wp + (size_t)j * ldw);
    };
    auto stsA = [&](int buf) {
        const uint32_t base = sb + buf * STAGE;
        #pragma unroll
        for (int it = 0; it < 4; ++it) {
            const int r = a_r0 + it * 32;
            uint4 u;
            u.x = f2tf(ra[it].x); u.y = f2tf(ra[it].y);
            u.z = f2tf(ra[it].z); u.w = f2tf(ra[it].w);
            const uint32_t off = r * 128 + ((a_kg * 16) ^ ((r & 7) << 4));
            *(uint4*)(sm + (base - sb) + off) = u;
        }
    };
    auto stsB = [&](int buf) {
        const uint32_t base = buf * STAGE + TILE_B;
        #pragma unroll
        for (int j = 0; j < 4; ++j) {           // n offset j: column of the 4x4 block
            uint4 c;
            c.x = f2tf(j == 0 ? rb[0].x : j == 1 ? rb[0].y : j == 2 ? rb[0].z : rb[0].w);
            c.y = f2tf(j == 0 ? rb[1].x : j == 1 ? rb[1].y : j == 2 ? rb[1].z : rb[1].w);
            c.z = f2tf(j == 0 ? rb[2].x : j == 1 ? rb[2].y : j == 2 ? rb[2].z : rb[2].w);
            c.w = f2tf(j == 0 ? rb[3].x : j == 1 ? rb[3].y : j == 2 ? rb[3].z : rb[3].w);
            const int row = b_n + j;
            const uint32_t off = row * 128 + ((b_k0 * 4) ^ ((row & 7) << 4));
            *(uint4*)(sm + base + off) = c;
        }
    };

    auto compute = [&](int buf) {
        const uint32_t Ab = sb + buf * STAGE;
        const uint32_t Bb = Ab + TILE_B;
        #pragma unroll
        for (int ks = 0; ks < 4; ++ks) {
            const int kb = ks * 32 + lkh;
            uint32_t af[2][4];
            #pragma unroll
            for (int mt = 0; mt < 2; ++mt) {
                const int row = wm * 32 + mt * 16 + lrow;
                ldsm4(af[mt], Ab + row * 128 + (kb ^ ((row & 7) << 4)));
            }
            uint32_t bf[4][4];
            #pragma unroll
            for (int ng = 0; ng < 4; ++ng) {
                const int row = wn * 64 + ng * 16 + lrow;
                ldsm4(bf[ng], Bb + row * 128 + (kb ^ ((row & 7) << 4)));
            }
            #pragma unroll
            for (int mt = 0; mt < 2; ++mt)
                #pragma unroll
                for (int nt = 0; nt < 8; ++nt)
                    mma_tf32(acc[mt][nt], af[mt],
                             bf[nt >> 1][nt & 1], bf[nt >> 1][(nt & 1) + 2]);
        }
    };

    const int S = K / BK;

    ldgA(0); ldgB(0);
    stsA(0); stsB(0);
    __syncthreads();

    #pragma unroll 1
    for (int kt = 0; kt < S; ++kt) {
        const int nxt = kt + 1;
        if (nxt < S) { ldgA(nxt * BK); ldgB(nxt * BK); }
        compute(kt & 1);
        if (nxt < S) { stsA(nxt & 1); stsB(nxt & 1); }
        __syncthreads();
    }

    // epilogue: +bias, optional relu, float2 stores
    #pragma unroll
    for (int mt = 0; mt < 2; ++mt) {
        const int r = m0 + wm * 32 + mt * 16 + g;
        #pragma unroll
        for (int nt = 0; nt < 8; ++nt) {
            const int c = n0 + wn * 64 + nt * 8 + tg * 2;
            const float b0v = bias[c], b1v = bias[c + 1];
            float v0 = acc[mt][nt][0] + b0v;
            float v1 = acc[mt][nt][1] + b1v;
            float v2 = acc[mt][nt][2] + b0v;
            float v3 = acc[mt][nt][3] + b1v;
            if (RELU) {
                v0 = fmaxf(v0, 0.f); v1 = fmaxf(v1, 0.f);
                v2 = fmaxf(v2, 0.f); v3 = fmaxf(v3, 0.f);
            }
            float2 p0; p0.x = v0; p0.y = v1;
            float2 p1; p1.x = v2; p1.y = v3;
            *(float2*)(C + (size_t)r * ldc + c)       = p0;
            *(float2*)(C + (size_t)(r + 8) * ldc + c) = p1;
        }
    }
}

} // anonymous namespace

extern "C" void kernel_launch(void* const* d_in, const int* in_sizes, int n_in,
                              void* d_out, int out_size) {
    (void)in_sizes; (void)n_in; (void)out_size;
    const float* x  = (const float*)d_in[0];  // [B, M, DIN]
    const float* W1 = (const float*)d_in[1];  // [M, DIN, DH]
    const float* b1 = (const float*)d_in[2];  // [M, DH]
    const float* W2 = (const float*)d_in[3];  // [M, DH, DOUT]
    const float* b2 = (const float*)d_in[4];  // [M, DOUT]
    float* out = (float*)d_out;               // [B, M, DOUT]

    float* h = nullptr;
    cudaGetSymbolAddress((void**)&h, g_h);

    cudaFuncSetAttribute(gemm_tf32<true>,  cudaFuncAttributeMaxDynamicSharedMemorySize, SMEM_DYN);
    cudaFuncSetAttribute(gemm_tf32<false>, cudaFuncAttributeMaxDynamicSharedMemorySize, SMEM_DYN);

    dim3 blk(256);

    // Layer 1: per m, h[b, n] = relu(x[b,:] @ W1 + b1)
    dim3 g1(DH / BN, Bsz / BM, Msl);
    gemm_tf32<true><<<g1, blk, SMEM_DYN>>>(
        x, W1, b1, h, DIN,
        /*aBatch*/ (long)DIN,        /*lda*/ Msl * DIN,
        /*wBatch*/ (long)DIN * DH,   /*ldw*/ DH,
        /*biasBatch*/ (long)DH,
        /*cBatch*/ (long)Bsz * DH,   /*ldc*/ DH);

    // Layer 2: per m, out[b, n] = h[b,:] @ W2 + b2
    dim3 g2(DOUT / BN, Bsz / BM, Msl);
    gemm_tf32<false><<<g2, blk, SMEM_DYN>>>(
        h, W2, b2, out, DH,
        /*aBatch*/ (long)Bsz * DH,   /*lda*/ DH,
        /*wBatch*/ (long)DH * DOUT,  /*ldw*/ DOUT,
        /*biasBatch*/ (long)DOUT,
        /*cBatch*/ (long)DOUT,       /*ldc*/ Msl * DOUT);
}